// round 4
// baseline (speedup 1.0000x reference)
#include <cuda_runtime.h>
#include <cstdint>

// ---------------- problem dims ----------------
constexpr int M = 8192, N = 4096, K = 4096, R = 16;

// ---------------- scratch ----------------
__device__ __align__(128) int8_t g_x1[(size_t)M * K];   // limb1 of x (scale 1/16)
__device__ __align__(128) int8_t g_x2[(size_t)M * K];   // limb2 of x (scale 1/4096)
__device__ __align__(128) int8_t g_w8[(size_t)N * K];   // weight as int8 (exact)
__device__ __align__(128) float  g_t [(size_t)M * R];   // x @ A^T fp32

// ---------------- asm helpers ----------------
__device__ __forceinline__ uint32_t smem_u32(const void* p) {
    uint32_t a;
    asm("{ .reg .u64 t; cvta.to.shared.u64 t, %1; cvt.u32.u64 %0, t; }"
        : "=r"(a) : "l"(p));
    return a;
}
__device__ __forceinline__ void cp16(uint32_t dst, const void* src) {
    asm volatile("cp.async.cg.shared.global [%0], [%1], 16;" :: "r"(dst), "l"(src));
}
#define CP_COMMIT() asm volatile("cp.async.commit_group;" ::: "memory")
#define CP_WAIT2()  asm volatile("cp.async.wait_group 2;" ::: "memory")
#define LDM4(rr, addr) \
    asm volatile("ldmatrix.sync.aligned.m8n8.x4.shared.b16 {%0,%1,%2,%3}, [%4];" \
        : "=r"((rr)[0]), "=r"((rr)[1]), "=r"((rr)[2]), "=r"((rr)[3]) : "r"(addr))
#define MMA_S8(d, a, b) \
    asm volatile("mma.sync.aligned.m16n8k32.row.col.s32.s8.s8.s32 " \
        "{%0,%1,%2,%3}, {%4,%5,%6,%7}, {%8,%9}, {%0,%1,%2,%3};" \
        : "+r"((d)[0]), "+r"((d)[1]), "+r"((d)[2]), "+r"((d)[3]) \
        : "r"((a)[0]), "r"((a)[1]), "r"((a)[2]), "r"((a)[3]), \
          "r"((b)[0]), "r"((b)[1]))

// ============================================================
// Prep 1: x fp32 -> two int8 limbs.  x ~= q1/16 + q2/4096
// ============================================================
__global__ void quant_x_kernel(const float* __restrict__ x) {
    int i = blockIdx.x * blockDim.x + threadIdx.x;   // float4 index
    if (i >= M * K / 4) return;
    float4 v = reinterpret_cast<const float4*>(x)[i];
    int q1x = max(-127, min(127, __float2int_rn(v.x * 16.f)));
    int q1y = max(-127, min(127, __float2int_rn(v.y * 16.f)));
    int q1z = max(-127, min(127, __float2int_rn(v.z * 16.f)));
    int q1w = max(-127, min(127, __float2int_rn(v.w * 16.f)));
    int q2x = max(-127, min(127, __float2int_rn((v.x - q1x * 0.0625f) * 4096.f)));
    int q2y = max(-127, min(127, __float2int_rn((v.y - q1y * 0.0625f) * 4096.f)));
    int q2z = max(-127, min(127, __float2int_rn((v.z - q1z * 0.0625f) * 4096.f)));
    int q2w = max(-127, min(127, __float2int_rn((v.w - q1w * 0.0625f) * 4096.f)));
    reinterpret_cast<char4*>(g_x1)[i] =
        make_char4((char)q1x, (char)q1y, (char)q1z, (char)q1w);
    reinterpret_cast<char4*>(g_x2)[i] =
        make_char4((char)q2x, (char)q2y, (char)q2z, (char)q2w);
}

// ============================================================
// Prep 2: weight int32 -> int8 (values already in [-128,127])
// ============================================================
__global__ void conv_w_kernel(const int* __restrict__ wq) {
    int i = blockIdx.x * blockDim.x + threadIdx.x;
    if (i >= N * K / 4) return;
    int4 v = reinterpret_cast<const int4*>(wq)[i];
    reinterpret_cast<char4*>(g_w8)[i] =
        make_char4((char)v.x, (char)v.y, (char)v.z, (char)v.w);
}

// ============================================================
// Prep 3: t = x @ A^T  (fp32)
// ============================================================
__global__ void lora_t_kernel(const float* __restrict__ x,
                              const float* __restrict__ A) {
    __shared__ float A_s[R * 512];
    const int tid = threadIdx.x;
    const int row = tid >> 3;
    const int l8  = tid & 7;
    const int m   = blockIdx.x * 32 + row;
    float acc[R];
#pragma unroll
    for (int r = 0; r < R; r++) acc[r] = 0.f;
    for (int kc = 0; kc < K; kc += 512) {
        __syncthreads();
        for (int i = tid; i < 2048; i += 256) {
            int rr = i >> 7, cc = i & 127;
            reinterpret_cast<float4*>(A_s)[i] =
                reinterpret_cast<const float4*>(A + (size_t)rr * K + kc)[cc];
        }
        __syncthreads();
        const float* xr = x + (size_t)m * K + kc;
        for (int k = l8 * 4; k < 512; k += 32) {
            float4 xv = *reinterpret_cast<const float4*>(xr + k);
#pragma unroll
            for (int r = 0; r < R; r++) {
                const float* Ar = A_s + r * 512 + k;
                acc[r] += xv.x * Ar[0] + xv.y * Ar[1] + xv.z * Ar[2] + xv.w * Ar[3];
            }
        }
    }
#pragma unroll
    for (int r = 0; r < R; r++) {
        float v = acc[r];
        v += __shfl_xor_sync(0xffffffffu, v, 1);
        v += __shfl_xor_sync(0xffffffffu, v, 2);
        v += __shfl_xor_sync(0xffffffffu, v, 4);
        if (l8 == 0) g_t[(size_t)m * R + r] = v;
    }
}

// ============================================================
// Main GEMM (IMMA s8): out = ws*( (q1@w)/16 + (q2@w)/4096 )
// 128x128 CTA tile, KS=64 per stage, 4-stage cp.async pipeline.
// 8 warps 4x2, warp tile 32x64, mma m16n8k32.
// ============================================================
constexpr int KS = 64;
constexpr int PS = 4;                 // pipeline stages
constexpr int NCHUNK = K / KS;        // 64
constexpr int ROWB = 80;              // padded row bytes (64 data + 16 pad)
constexpr int A_ST = 128 * ROWB;      // 10240 per operand plane
constexpr int STAGE = 3 * A_ST;       // 30720
constexpr int SMEM_GEMM = PS * STAGE; // 122880

__global__ void __launch_bounds__(256, 1)
gemm_kernel(const float* __restrict__ ws, float* __restrict__ out) {
    extern __shared__ __align__(128) char smem[];
    const uint32_t sb = smem_u32(smem);
    const int tid  = threadIdx.x;
    const int lane = tid & 31;
    const int wid  = tid >> 5;
    const int wm   = wid >> 1;          // 0..3 -> rows wm*32
    const int wn   = wid & 1;           // 0..1 -> cols wn*64
    const int m0 = blockIdx.y * 128;
    const int n0 = blockIdx.x * 128;

    // cp.async mapping: thread covers 16B chunks (r0,c0) and (r0+64,c0)
    const int r0 = tid >> 2;
    const int c0 = (tid & 3) * 16;
    const uint32_t dst0 = (uint32_t)(r0 * ROWB + c0);
    const uint32_t dst1 = (uint32_t)((r0 + 64) * ROWB + c0);
    const int8_t* pa1a = g_x1 + (size_t)(m0 + r0) * K + c0;
    const int8_t* pa1b = pa1a + (size_t)64 * K;
    const int8_t* pa2a = g_x2 + (size_t)(m0 + r0) * K + c0;
    const int8_t* pa2b = pa2a + (size_t)64 * K;
    const int8_t* pba  = g_w8 + (size_t)(n0 + r0) * K + c0;
    const int8_t* pbb  = pba + (size_t)64 * K;

    // ldmatrix lane address offsets
    const int arow = wm * 32 + (lane & 7) + ((lane >> 3) & 1) * 8;
    const uint32_t aoff = (uint32_t)(arow * ROWB + (lane >> 4) * 16);
    const int brow = wn * 64 + (lane & 15);
    const uint32_t boff = (uint32_t)(brow * ROWB + (lane >> 4) * 16);

    int acc1[2][8][4] = {};
    int acc2[2][8][4] = {};

    // prologue: stages 0..2 <- chunks 0..2
#pragma unroll
    for (int s = 0; s < PS - 1; s++) {
        const uint32_t st = sb + s * STAGE;
        cp16(st + dst0, pa1a);              cp16(st + dst1, pa1b);
        cp16(st + A_ST + dst0, pa2a);       cp16(st + A_ST + dst1, pa2b);
        cp16(st + 2 * A_ST + dst0, pba);    cp16(st + 2 * A_ST + dst1, pbb);
        pa1a += KS; pa1b += KS; pa2a += KS; pa2b += KS; pba += KS; pbb += KS;
        CP_COMMIT();
    }

    for (int j = 0; j < NCHUNK; j++) {
        CP_WAIT2();
        __syncthreads();
        // issue chunk j+3 into stage (j+3)&3 (== (j-1)&3, already consumed)
        if (j + PS - 1 < NCHUNK) {
            const uint32_t st = sb + ((j + PS - 1) & 3) * STAGE;
            cp16(st + dst0, pa1a);              cp16(st + dst1, pa1b);
            cp16(st + A_ST + dst0, pa2a);       cp16(st + A_ST + dst1, pa2b);
            cp16(st + 2 * A_ST + dst0, pba);    cp16(st + 2 * A_ST + dst1, pbb);
            pa1a += KS; pa1b += KS; pa2a += KS; pa2b += KS; pba += KS; pbb += KS;
        }
        CP_COMMIT();

        // compute chunk j from stage j&3
        const uint32_t sa1 = sb + (j & 3) * STAGE;
        const uint32_t sa2 = sa1 + A_ST;
        const uint32_t sbb = sa1 + 2 * A_ST;
#pragma unroll
        for (int c = 0; c < 2; c++) {        // two k32 steps per chunk
            uint32_t a1f[2][4], a2f[2][4], bfr[8][2];
#pragma unroll
            for (int mi = 0; mi < 2; mi++) {
                LDM4(a1f[mi], sa1 + aoff + mi * (16 * ROWB) + c * 32);
                LDM4(a2f[mi], sa2 + aoff + mi * (16 * ROWB) + c * 32);
            }
#pragma unroll
            for (int jj = 0; jj < 4; jj++) {
                uint32_t r[4];
                LDM4(r, sbb + boff + jj * (16 * ROWB) + c * 32);
                bfr[2 * jj][0]     = r[0];  bfr[2 * jj][1]     = r[2];
                bfr[2 * jj + 1][0] = r[1];  bfr[2 * jj + 1][1] = r[3];
            }
#pragma unroll
            for (int mi = 0; mi < 2; mi++)
#pragma unroll
                for (int nj = 0; nj < 8; nj++) {
                    MMA_S8(acc1[mi][nj], a1f[mi], bfr[nj]);
                    MMA_S8(acc2[mi][nj], a2f[mi], bfr[nj]);
                }
        }
    }

    // epilogue: combine limbs, scale, store
    const float sc = ws[0];
    const float s1 = 1.0f / 16.0f, s2 = 1.0f / 4096.0f;
    const int quad = lane >> 2, qi = lane & 3;
#pragma unroll
    for (int mi = 0; mi < 2; mi++) {
        const int r = m0 + wm * 32 + mi * 16 + quad;
#pragma unroll
        for (int nj = 0; nj < 8; nj++) {
            const int c = n0 + wn * 64 + nj * 8 + 2 * qi;
            float2 v0, v1;
            v0.x = sc * ((float)acc1[mi][nj][0] * s1 + (float)acc2[mi][nj][0] * s2);
            v0.y = sc * ((float)acc1[mi][nj][1] * s1 + (float)acc2[mi][nj][1] * s2);
            v1.x = sc * ((float)acc1[mi][nj][2] * s1 + (float)acc2[mi][nj][2] * s2);
            v1.y = sc * ((float)acc1[mi][nj][3] * s1 + (float)acc2[mi][nj][3] * s2);
            *reinterpret_cast<float2*>(out + (size_t)r * N + c) = v0;
            *reinterpret_cast<float2*>(out + (size_t)(r + 8) * N + c) = v1;
        }
    }
}

// ============================================================
// Post: out += 2 * t @ lB^T   (rank-16 update, RMW)
// Block: 128 rows x 1024 cols. lB strip + t rows staged in smem.
// ============================================================
constexpr int SMEM_LORA = (1024 * R + 128 * R) * 4;   // 73728

__global__ void __launch_bounds__(256)
lora_add_kernel(float* __restrict__ out, const float* __restrict__ lB) {
    extern __shared__ float sm[];
    float* bs = sm;              // [1024][16]
    float* ts = sm + 1024 * R;   // [128][16]
    const int tid = threadIdx.x;
    const int n0 = blockIdx.x * 1024;
    const int m0 = blockIdx.y * 128;

    for (int i = tid; i < 1024 * R / 4; i += 256)
        reinterpret_cast<float4*>(bs)[i] =
            reinterpret_cast<const float4*>(lB + (size_t)n0 * R)[i];
    for (int i = tid; i < 128 * R / 4; i += 256)
        reinterpret_cast<float4*>(ts)[i] =
            reinterpret_cast<const float4*>(g_t + (size_t)m0 * R)[i];
    __syncthreads();

    // this thread owns 4 columns: n = n0 + tid*4 + {0..3}
    float br[4][R];
#pragma unroll
    for (int c = 0; c < 4; c++)
#pragma unroll
        for (int q = 0; q < R / 4; q++)
            reinterpret_cast<float4*>(br[c])[q] =
                reinterpret_cast<float4*>(bs + (tid * 4 + c) * R)[q];

    for (int rg = 0; rg < 32; rg++) {
        float tr[4][R];
#pragma unroll
        for (int rr = 0; rr < 4; rr++)
#pragma unroll
            for (int q = 0; q < R / 4; q++)
                reinterpret_cast<float4*>(tr[rr])[q] =
                    reinterpret_cast<float4*>(ts + (rg * 4 + rr) * R)[q];
#pragma unroll
        for (int rr = 0; rr < 4; rr++) {
            float* op = out + (size_t)(m0 + rg * 4 + rr) * N + n0 + tid * 4;
            float4 o = *reinterpret_cast<float4*>(op);
            float a0 = 0.f, a1 = 0.f, a2 = 0.f, a3 = 0.f;
#pragma unroll
            for (int k = 0; k < R; k++) {
                float tv = tr[rr][k];
                a0 += tv * br[0][k];
                a1 += tv * br[1][k];
                a2 += tv * br[2][k];
                a3 += tv * br[3][k];
            }
            o.x += 2.f * a0; o.y += 2.f * a1; o.z += 2.f * a2; o.w += 2.f * a3;
            *reinterpret_cast<float4*>(op) = o;
        }
    }
}

// ============================================================
// launch
// ============================================================
extern "C" void kernel_launch(void* const* d_in, const int* in_sizes, int n_in,
                              void* d_out, int out_size) {
    const float* x  = (const float*)d_in[0];
    const int*   wq = (const int*)d_in[1];
    const float* ws = (const float*)d_in[2];
    const float* lA = (const float*)d_in[3];
    const float* lB = (const float*)d_in[4];
    float* out = (float*)d_out;

    quant_x_kernel<<<(M * K / 4 + 255) / 256, 256>>>(x);
    conv_w_kernel<<<(N * K / 4 + 255) / 256, 256>>>(wq);
    lora_t_kernel<<<M / 32, 256>>>(x, lA);

    cudaFuncSetAttribute(gemm_kernel,
                         cudaFuncAttributeMaxDynamicSharedMemorySize, SMEM_GEMM);
    dim3 grid(N / 128, M / 128);   // 32 x 64
    gemm_kernel<<<grid, 256, SMEM_GEMM>>>(ws, out);

    cudaFuncSetAttribute(lora_add_kernel,
                         cudaFuncAttributeMaxDynamicSharedMemorySize, SMEM_LORA);
    lora_add_kernel<<<dim3(N / 1024, M / 128), 256, SMEM_LORA>>>(out, lB);
}

// round 6
// speedup vs baseline: 3.4857x; 3.4857x over previous
#include <cuda_runtime.h>
#include <cuda_fp16.h>
#include <cstdint>

// ---------------- problem dims ----------------
constexpr int M = 8192, N = 4096, KX = 4096, R = 16;
constexpr int KE = 4160;            // 4096 + 16 lora + 48 zero pad = 65*64

// ---------------- scratch ----------------
__device__ __align__(128) __half g_x[(size_t)M * KE];   // x (+t) as fp16, 68 MB
__device__ __align__(128) __half g_w[(size_t)N * KE];   // W (+2B/ws) as fp16, 34 MB

// ---------------- asm helpers ----------------
__device__ __forceinline__ uint32_t smem_u32(const void* p) {
    uint32_t a;
    asm("{ .reg .u64 t; cvta.to.shared.u64 t, %1; cvt.u32.u64 %0, t; }"
        : "=r"(a) : "l"(p));
    return a;
}
__device__ __forceinline__ void cp16(uint32_t dst, const void* src) {
    asm volatile("cp.async.cg.shared.global [%0], [%1], 16;" :: "r"(dst), "l"(src));
}
#define CP_COMMIT() asm volatile("cp.async.commit_group;" ::: "memory")
#define CP_WAIT2()  asm volatile("cp.async.wait_group 2;" ::: "memory")
#define LDM4(rr, addr) \
    asm volatile("ldmatrix.sync.aligned.m8n8.x4.shared.b16 {%0,%1,%2,%3}, [%4];" \
        : "=r"((rr)[0]), "=r"((rr)[1]), "=r"((rr)[2]), "=r"((rr)[3]) : "r"(addr))
#define MMA_F16(d, a, b) \
    asm volatile("mma.sync.aligned.m16n8k16.row.col.f32.f16.f16.f32 " \
        "{%0,%1,%2,%3}, {%4,%5,%6,%7}, {%8,%9}, {%0,%1,%2,%3};" \
        : "+f"((d)[0]), "+f"((d)[1]), "+f"((d)[2]), "+f"((d)[3]) \
        : "r"((a)[0]), "r"((a)[1]), "r"((a)[2]), "r"((a)[3]), \
          "r"((b)[0]), "r"((b)[1]))

// ============================================================
// Prep 1: x fp32 -> fp16 plane (stride KE); pad/lora cols zeroed here
// ============================================================
__global__ void conv_x_kernel(const float* __restrict__ x) {
    int i = blockIdx.x * blockDim.x + threadIdx.x;   // 4-elem group in KE row
    const int KQ = KE / 4;                            // 1040
    if (i >= M * KQ) return;
    int row = i / KQ;
    int col = (i - row * KQ) * 4;
    __half2 h0, h1;
    if (col < KX) {
        float4 v = *reinterpret_cast<const float4*>(x + (size_t)row * KX + col);
        h0 = __floats2half2_rn(v.x, v.y);
        h1 = __floats2half2_rn(v.z, v.w);
    } else {
        h0 = h1 = __floats2half2_rn(0.f, 0.f);
    }
    size_t o = (size_t)row * KE + col;
    *reinterpret_cast<__half2*>(g_x + o)     = h0;
    *reinterpret_cast<__half2*>(g_x + o + 2) = h1;
}

// ============================================================
// Prep 2: W int32 -> fp16 exact; cols [4096,4112) = (2/ws)*lB; pad zero
// ============================================================
__global__ void conv_w_kernel(const int* __restrict__ wq,
                              const float* __restrict__ ws,
                              const float* __restrict__ lB) {
    int i = blockIdx.x * blockDim.x + threadIdx.x;
    const int KQ = KE / 4;
    if (i >= N * KQ) return;
    int row = i / KQ;
    int col = (i - row * KQ) * 4;
    __half2 o0, o1;
    if (col < KX) {
        int4 v = *reinterpret_cast<const int4*>(wq + (size_t)row * KX + col);
        o0 = __floats2half2_rn((float)v.x, (float)v.y);
        o1 = __floats2half2_rn((float)v.z, (float)v.w);
    } else if (col < KX + R) {
        float inv2 = 2.0f / ws[0];
        const float* b = lB + (size_t)row * R + (col - KX);
        o0 = __floats2half2_rn(inv2 * b[0], inv2 * b[1]);
        o1 = __floats2half2_rn(inv2 * b[2], inv2 * b[3]);
    } else {
        o0 = o1 = __floats2half2_rn(0.f, 0.f);
    }
    size_t o = (size_t)row * KE + col;
    *reinterpret_cast<__half2*>(g_w + o)     = o0;
    *reinterpret_cast<__half2*>(g_w + o + 2) = o1;
}

// ============================================================
// Prep 3: t = x @ A^T (fp32), written as fp16 into lora K-columns of g_x
// ============================================================
__global__ void lora_t_kernel(const float* __restrict__ x,
                              const float* __restrict__ A) {
    __shared__ float A_s[R * 512];
    const int tid = threadIdx.x;
    const int row = tid >> 3;
    const int l8  = tid & 7;
    const int m   = blockIdx.x * 32 + row;
    float acc[R];
#pragma unroll
    for (int r = 0; r < R; r++) acc[r] = 0.f;
    for (int kc = 0; kc < KX; kc += 512) {
        __syncthreads();
        for (int i = tid; i < 2048; i += 256) {
            int rr = i >> 7, cc = i & 127;
            reinterpret_cast<float4*>(A_s)[i] =
                reinterpret_cast<const float4*>(A + (size_t)rr * KX + kc)[cc];
        }
        __syncthreads();
        const float* xr = x + (size_t)m * KX + kc;
        for (int k = l8 * 4; k < 512; k += 32) {
            float4 xv = *reinterpret_cast<const float4*>(xr + k);
#pragma unroll
            for (int r = 0; r < R; r++) {
                const float* Ar = A_s + r * 512 + k;
                acc[r] += xv.x * Ar[0] + xv.y * Ar[1] + xv.z * Ar[2] + xv.w * Ar[3];
            }
        }
    }
#pragma unroll
    for (int r = 0; r < R; r++) {
        float v = acc[r];
        v += __shfl_xor_sync(0xffffffffu, v, 1);
        v += __shfl_xor_sync(0xffffffffu, v, 2);
        v += __shfl_xor_sync(0xffffffffu, v, 4);
        if (l8 == 0) g_x[(size_t)m * KE + KX + r] = __float2half_rn(v);
    }
}

// ============================================================
// Main GEMM (HMMA fp16): out = ws * (x_ext @ W_ext^T)
// 128x128 CTA tile, KS=64, 4-stage cp.async pipeline,
// 8 warps 4x2, warp tile 32x64, mma m16n8k16 f16->f32.
// ============================================================
constexpr int KS = 64;                  // K elems per chunk (128 B/row fp16)
constexpr int PS = 4;                   // pipeline stages
constexpr int NCHUNK = KE / KS;         // 65
constexpr int ROWB = 144;               // 128 data + 16 pad (conflict-free ldmatrix)
constexpr int A_ST = 128 * ROWB;        // 18432 per operand plane
constexpr int STAGE = 2 * A_ST;         // 36864
constexpr int SMEM_GEMM = PS * STAGE;   // 147456

__global__ void __launch_bounds__(256, 1)
gemm_kernel(const float* __restrict__ ws, float* __restrict__ out) {
    extern __shared__ __align__(128) char smem[];
    const uint32_t sb = smem_u32(smem);
    const int tid  = threadIdx.x;
    const int lane = tid & 31;
    const int wid  = tid >> 5;
    const int wm   = wid >> 1;          // 0..3 -> rows wm*32
    const int wn   = wid & 1;           // 0..1 -> cols wn*64
    const int m0 = blockIdx.y * 128;
    const int n0 = blockIdx.x * 128;

    // cp.async mapping: per plane, thread covers rows {r0, r0+64} x cols {c0, c0+64B}
    const int r0 = tid >> 2;            // 0..63
    const int c0 = (tid & 3) * 16;      // byte col 0/16/32/48
    const uint32_t d00 = (uint32_t)(r0 * ROWB + c0);
    const uint32_t d01 = d00 + 64;
    const uint32_t d10 = d00 + 64 * ROWB;
    const uint32_t d11 = d10 + 64;
    const __half* pa = g_x + (size_t)(m0 + r0) * KE + c0 / 2;
    const __half* pb = g_w + (size_t)(n0 + r0) * KE + c0 / 2;
    const size_t rstep = (size_t)64 * KE;

    // ldmatrix lane offsets
    const int arow = wm * 32 + (lane & 7) + ((lane >> 3) & 1) * 8;
    const uint32_t aoff = (uint32_t)(arow * ROWB) + ((lane >> 4) * 16);
    const int brow = wn * 64 + (lane & 7) + (lane >> 4) * 8;
    const uint32_t boff = (uint32_t)(brow * ROWB) + (((lane >> 3) & 1) * 16);

    float acc[2][8][4] = {};

    // prologue: stages 0..2 <- chunks 0..2
#pragma unroll
    for (int s = 0; s < PS - 1; s++) {
        const uint32_t st = sb + s * STAGE;
        cp16(st + d00, pa);          cp16(st + d01, pa + 32);
        cp16(st + d10, pa + rstep);  cp16(st + d11, pa + rstep + 32);
        cp16(st + A_ST + d00, pb);          cp16(st + A_ST + d01, pb + 32);
        cp16(st + A_ST + d10, pb + rstep);  cp16(st + A_ST + d11, pb + rstep + 32);
        pa += KS; pb += KS;
        CP_COMMIT();
    }

    for (int j = 0; j < NCHUNK; j++) {
        CP_WAIT2();
        __syncthreads();
        if (j + PS - 1 < NCHUNK) {
            const uint32_t st = sb + ((j + PS - 1) & 3) * STAGE;
            cp16(st + d00, pa);          cp16(st + d01, pa + 32);
            cp16(st + d10, pa + rstep);  cp16(st + d11, pa + rstep + 32);
            cp16(st + A_ST + d00, pb);          cp16(st + A_ST + d01, pb + 32);
            cp16(st + A_ST + d10, pb + rstep);  cp16(st + A_ST + d11, pb + rstep + 32);
            pa += KS; pb += KS;
        }
        CP_COMMIT();

        const uint32_t sa = sb + (j & 3) * STAGE;
        const uint32_t sbp = sa + A_ST;
#pragma unroll
        for (int c = 0; c < 4; c++) {       // four k16 steps per chunk
            uint32_t af[2][4], bf[8][2];
#pragma unroll
            for (int mi = 0; mi < 2; mi++)
                LDM4(af[mi], sa + aoff + mi * (16 * ROWB) + c * 32);
#pragma unroll
            for (int jj = 0; jj < 4; jj++) {
                uint32_t r[4];
                LDM4(r, sbp + boff + jj * (16 * ROWB) + c * 32);
                bf[2 * jj][0]     = r[0];  bf[2 * jj][1]     = r[1];
                bf[2 * jj + 1][0] = r[2];  bf[2 * jj + 1][1] = r[3];
            }
#pragma unroll
            for (int mi = 0; mi < 2; mi++)
#pragma unroll
                for (int nj = 0; nj < 8; nj++)
                    MMA_F16(acc[mi][nj], af[mi], bf[nj]);
        }
    }

    // epilogue: scale by ws, store (lora already folded into K)
    const float sc = ws[0];
    const int quad = lane >> 2, qi = lane & 3;
#pragma unroll
    for (int mi = 0; mi < 2; mi++) {
        const int r = m0 + wm * 32 + mi * 16 + quad;
#pragma unroll
        for (int nj = 0; nj < 8; nj++) {
            const int cc = n0 + wn * 64 + nj * 8 + 2 * qi;
            float2 v0, v1;
            v0.x = sc * acc[mi][nj][0];
            v0.y = sc * acc[mi][nj][1];
            v1.x = sc * acc[mi][nj][2];
            v1.y = sc * acc[mi][nj][3];
            *reinterpret_cast<float2*>(out + (size_t)r * N + cc) = v0;
            *reinterpret_cast<float2*>(out + (size_t)(r + 8) * N + cc) = v1;
        }
    }
}

// ============================================================
// launch
// ============================================================
extern "C" void kernel_launch(void* const* d_in, const int* in_sizes, int n_in,
                              void* d_out, int out_size) {
    const float* x  = (const float*)d_in[0];
    const int*   wq = (const int*)d_in[1];
    const float* ws = (const float*)d_in[2];
    const float* lA = (const float*)d_in[3];
    const float* lB = (const float*)d_in[4];
    float* out = (float*)d_out;

    conv_x_kernel<<<(M * (KE / 4) + 255) / 256, 256>>>(x);
    conv_w_kernel<<<(N * (KE / 4) + 255) / 256, 256>>>(wq, ws, lB);
    lora_t_kernel<<<M / 32, 256>>>(x, lA);

    cudaFuncSetAttribute(gemm_kernel,
                         cudaFuncAttributeMaxDynamicSharedMemorySize, SMEM_GEMM);
    dim3 grid(N / 128, M / 128);   // 32 x 64
    gemm_kernel<<<grid, 256, SMEM_GEMM>>>(ws, out);
}

// round 7
// speedup vs baseline: 4.0000x; 1.1476x over previous
#include <cuda_runtime.h>
#include <cuda_fp16.h>
#include <cstdint>

// ---------------- problem dims ----------------
constexpr int M = 8192, N = 4096, KX = 4096, R = 16;
constexpr int KE = 4160;            // 4096 + 16 lora + 48 zero pad = 65*64

// ---------------- scratch ----------------
__device__ __align__(128) __half g_x[(size_t)M * KE];   // x (+t) as fp16, 68 MB
__device__ __align__(128) __half g_w[(size_t)N * KE];   // W (+2B/ws) as fp16, 34 MB

// ---------------- asm helpers ----------------
__device__ __forceinline__ uint32_t smem_u32(const void* p) {
    uint32_t a;
    asm("{ .reg .u64 t; cvta.to.shared.u64 t, %1; cvt.u32.u64 %0, t; }"
        : "=r"(a) : "l"(p));
    return a;
}
__device__ __forceinline__ void cp16(uint32_t dst, const void* src) {
    asm volatile("cp.async.cg.shared.global [%0], [%1], 16;" :: "r"(dst), "l"(src));
}
#define CP_COMMIT() asm volatile("cp.async.commit_group;" ::: "memory")
#define CP_WAIT1()  asm volatile("cp.async.wait_group 1;" ::: "memory")
#define LDM4(rr, addr) \
    asm volatile("ldmatrix.sync.aligned.m8n8.x4.shared.b16 {%0,%1,%2,%3}, [%4];" \
        : "=r"((rr)[0]), "=r"((rr)[1]), "=r"((rr)[2]), "=r"((rr)[3]) : "r"(addr))
#define MMA_F16(d, a, b) \
    asm volatile("mma.sync.aligned.m16n8k16.row.col.f32.f16.f16.f32 " \
        "{%0,%1,%2,%3}, {%4,%5,%6,%7}, {%8,%9}, {%0,%1,%2,%3};" \
        : "+f"((d)[0]), "+f"((d)[1]), "+f"((d)[2]), "+f"((d)[3]) \
        : "r"((a)[0]), "r"((a)[1]), "r"((a)[2]), "r"((a)[3]), \
          "r"((b)[0]), "r"((b)[1]))

// ============================================================
// Prep 1: x fp32 -> fp16 plane (stride KE); pad/lora cols zeroed here
// ============================================================
__global__ void conv_x_kernel(const float* __restrict__ x) {
    int i = blockIdx.x * blockDim.x + threadIdx.x;   // 4-elem group in KE row
    const int KQ = KE / 4;                            // 1040
    if (i >= M * KQ) return;
    int row = i / KQ;
    int col = (i - row * KQ) * 4;
    __half2 h0, h1;
    if (col < KX) {
        float4 v = *reinterpret_cast<const float4*>(x + (size_t)row * KX + col);
        h0 = __floats2half2_rn(v.x, v.y);
        h1 = __floats2half2_rn(v.z, v.w);
    } else {
        h0 = h1 = __floats2half2_rn(0.f, 0.f);
    }
    size_t o = (size_t)row * KE + col;
    *reinterpret_cast<__half2*>(g_x + o)     = h0;
    *reinterpret_cast<__half2*>(g_x + o + 2) = h1;
}

// ============================================================
// Prep 2: W int32 -> fp16 exact; cols [4096,4112) = (2/ws)*lB; pad zero
// ============================================================
__global__ void conv_w_kernel(const int* __restrict__ wq,
                              const float* __restrict__ ws,
                              const float* __restrict__ lB) {
    int i = blockIdx.x * blockDim.x + threadIdx.x;
    const int KQ = KE / 4;
    if (i >= N * KQ) return;
    int row = i / KQ;
    int col = (i - row * KQ) * 4;
    __half2 o0, o1;
    if (col < KX) {
        int4 v = *reinterpret_cast<const int4*>(wq + (size_t)row * KX + col);
        o0 = __floats2half2_rn((float)v.x, (float)v.y);
        o1 = __floats2half2_rn((float)v.z, (float)v.w);
    } else if (col < KX + R) {
        float inv2 = 2.0f / ws[0];
        const float* b = lB + (size_t)row * R + (col - KX);
        o0 = __floats2half2_rn(inv2 * b[0], inv2 * b[1]);
        o1 = __floats2half2_rn(inv2 * b[2], inv2 * b[3]);
    } else {
        o0 = o1 = __floats2half2_rn(0.f, 0.f);
    }
    size_t o = (size_t)row * KE + col;
    *reinterpret_cast<__half2*>(g_w + o)     = o0;
    *reinterpret_cast<__half2*>(g_w + o + 2) = o1;
}

// ============================================================
// Prep 3: t = x @ A^T (fp32), written as fp16 into lora K-columns of g_x
// ============================================================
__global__ void lora_t_kernel(const float* __restrict__ x,
                              const float* __restrict__ A) {
    __shared__ float A_s[R * 512];
    const int tid = threadIdx.x;
    const int row = tid >> 3;
    const int l8  = tid & 7;
    const int m   = blockIdx.x * 32 + row;
    float acc[R];
#pragma unroll
    for (int r = 0; r < R; r++) acc[r] = 0.f;
    for (int kc = 0; kc < KX; kc += 512) {
        __syncthreads();
        for (int i = tid; i < 2048; i += 256) {
            int rr = i >> 7, cc = i & 127;
            reinterpret_cast<float4*>(A_s)[i] =
                reinterpret_cast<const float4*>(A + (size_t)rr * KX + kc)[cc];
        }
        __syncthreads();
        const float* xr = x + (size_t)m * KX + kc;
        for (int k = l8 * 4; k < 512; k += 32) {
            float4 xv = *reinterpret_cast<const float4*>(xr + k);
#pragma unroll
            for (int r = 0; r < R; r++) {
                const float* Ar = A_s + r * 512 + k;
                acc[r] += xv.x * Ar[0] + xv.y * Ar[1] + xv.z * Ar[2] + xv.w * Ar[3];
            }
        }
    }
#pragma unroll
    for (int r = 0; r < R; r++) {
        float v = acc[r];
        v += __shfl_xor_sync(0xffffffffu, v, 1);
        v += __shfl_xor_sync(0xffffffffu, v, 2);
        v += __shfl_xor_sync(0xffffffffu, v, 4);
        if (l8 == 0) g_x[(size_t)m * KE + KX + r] = __float2half_rn(v);
    }
}

// ============================================================
// Main GEMM (HMMA fp16): out = ws * (x_ext @ W_ext^T)
// 128x128 CTA tile, KS=64, 3-stage cp.async pipeline, 2 CTAs/SM,
// 8 warps 4x2, warp tile 32x64, mma m16n8k16 f16->f32.
// ============================================================
constexpr int KS = 64;                  // K elems per chunk (128 B/row fp16)
constexpr int PS = 3;                   // pipeline stages
constexpr int NCHUNK = KE / KS;         // 65
constexpr int ROWB = 144;               // 128 data + 16 pad (conflict-free ldmatrix)
constexpr int A_ST = 128 * ROWB;        // 18432 per operand plane
constexpr int STAGE = 2 * A_ST;         // 36864
constexpr int SMEM_GEMM = PS * STAGE;   // 110592 -> 2 CTAs/SM (221KB < 228KB)

__global__ void __launch_bounds__(256, 2)
gemm_kernel(const float* __restrict__ ws, float* __restrict__ out) {
    extern __shared__ __align__(128) char smem[];
    const uint32_t sb = smem_u32(smem);
    const int tid  = threadIdx.x;
    const int lane = tid & 31;
    const int wid  = tid >> 5;
    const int wm   = wid >> 1;          // 0..3 -> rows wm*32
    const int wn   = wid & 1;           // 0..1 -> cols wn*64
    const int m0 = blockIdx.y * 128;
    const int n0 = blockIdx.x * 128;

    // cp.async mapping: per plane, thread covers rows {r0, r0+64} x cols {c0, c0+64B}
    const int r0 = tid >> 2;            // 0..63
    const int c0 = (tid & 3) * 16;      // byte col 0/16/32/48
    const uint32_t d00 = (uint32_t)(r0 * ROWB + c0);
    const uint32_t d01 = d00 + 64;
    const uint32_t d10 = d00 + 64 * ROWB;
    const uint32_t d11 = d10 + 64;
    const __half* pa = g_x + (size_t)(m0 + r0) * KE + c0 / 2;
    const __half* pb = g_w + (size_t)(n0 + r0) * KE + c0 / 2;
    const size_t rstep = (size_t)64 * KE;

    // ldmatrix lane offsets
    const int arow = wm * 32 + (lane & 7) + ((lane >> 3) & 1) * 8;
    const uint32_t aoff = (uint32_t)(arow * ROWB) + ((lane >> 4) * 16);
    const int brow = wn * 64 + (lane & 7) + (lane >> 4) * 8;
    const uint32_t boff = (uint32_t)(brow * ROWB) + (((lane >> 3) & 1) * 16);

    float acc[2][8][4] = {};

    // prologue: stages 0,1 <- chunks 0,1
#pragma unroll
    for (int s = 0; s < PS - 1; s++) {
        const uint32_t st = sb + s * STAGE;
        cp16(st + d00, pa);          cp16(st + d01, pa + 32);
        cp16(st + d10, pa + rstep);  cp16(st + d11, pa + rstep + 32);
        cp16(st + A_ST + d00, pb);          cp16(st + A_ST + d01, pb + 32);
        cp16(st + A_ST + d10, pb + rstep);  cp16(st + A_ST + d11, pb + rstep + 32);
        pa += KS; pb += KS;
        CP_COMMIT();
    }

    for (int j = 0; j < NCHUNK; j++) {
        CP_WAIT1();                       // chunk j ready; j+1 may be in flight
        __syncthreads();
        if (j + PS - 1 < NCHUNK) {        // refill stage (j-1)%3 with chunk j+2
            const int s = (j + PS - 1) % PS;
            const uint32_t st = sb + s * STAGE;
            cp16(st + d00, pa);          cp16(st + d01, pa + 32);
            cp16(st + d10, pa + rstep);  cp16(st + d11, pa + rstep + 32);
            cp16(st + A_ST + d00, pb);          cp16(st + A_ST + d01, pb + 32);
            cp16(st + A_ST + d10, pb + rstep);  cp16(st + A_ST + d11, pb + rstep + 32);
            pa += KS; pb += KS;
        }
        CP_COMMIT();

        const uint32_t sa = sb + (j % PS) * STAGE;
        const uint32_t sbp = sa + A_ST;
#pragma unroll
        for (int c = 0; c < 4; c++) {       // four k16 steps per chunk
            uint32_t af[2][4], bf[8][2];
#pragma unroll
            for (int mi = 0; mi < 2; mi++)
                LDM4(af[mi], sa + aoff + mi * (16 * ROWB) + c * 32);
#pragma unroll
            for (int jj = 0; jj < 4; jj++) {
                uint32_t r[4];
                LDM4(r, sbp + boff + jj * (16 * ROWB) + c * 32);
                bf[2 * jj][0]     = r[0];  bf[2 * jj][1]     = r[1];
                bf[2 * jj + 1][0] = r[2];  bf[2 * jj + 1][1] = r[3];
            }
#pragma unroll
            for (int mi = 0; mi < 2; mi++)
#pragma unroll
                for (int nj = 0; nj < 8; nj++)
                    MMA_F16(acc[mi][nj], af[mi], bf[nj]);
        }
    }

    // epilogue: scale by ws, store (lora already folded into K)
    const float sc = ws[0];
    const int quad = lane >> 2, qi = lane & 3;
#pragma unroll
    for (int mi = 0; mi < 2; mi++) {
        const int r = m0 + wm * 32 + mi * 16 + quad;
#pragma unroll
        for (int nj = 0; nj < 8; nj++) {
            const int cc = n0 + wn * 64 + nj * 8 + 2 * qi;
            float2 v0, v1;
            v0.x = sc * acc[mi][nj][0];
            v0.y = sc * acc[mi][nj][1];
            v1.x = sc * acc[mi][nj][2];
            v1.y = sc * acc[mi][nj][3];
            *reinterpret_cast<float2*>(out + (size_t)r * N + cc) = v0;
            *reinterpret_cast<float2*>(out + (size_t)(r + 8) * N + cc) = v1;
        }
    }
}

// ============================================================
// launch
// ============================================================
extern "C" void kernel_launch(void* const* d_in, const int* in_sizes, int n_in,
                              void* d_out, int out_size) {
    const float* x  = (const float*)d_in[0];
    const int*   wq = (const int*)d_in[1];
    const float* ws = (const float*)d_in[2];
    const float* lA = (const float*)d_in[3];
    const float* lB = (const float*)d_in[4];
    float* out = (float*)d_out;

    conv_x_kernel<<<(M * (KE / 4) + 255) / 256, 256>>>(x);
    conv_w_kernel<<<(N * (KE / 4) + 255) / 256, 256>>>(wq, ws, lB);
    lora_t_kernel<<<M / 32, 256>>>(x, lA);

    cudaFuncSetAttribute(gemm_kernel,
                         cudaFuncAttributeMaxDynamicSharedMemorySize, SMEM_GEMM);
    dim3 grid(N / 128, M / 128);   // 32 x 64
    gemm_kernel<<<grid, 256, SMEM_GEMM>>>(ws, out);
}

// round 8
// speedup vs baseline: 4.3179x; 1.0795x over previous
#include <cuda_runtime.h>
#include <cuda_fp16.h>
#include <cstdint>

// ---------------- problem dims ----------------
constexpr int M = 8192, N = 4096, KX = 4096, R = 16;
constexpr int KE = 4160;            // 4096 + 16 lora + 48 zero pad = 65*64

// ---------------- scratch ----------------
__device__ __align__(128) __half g_x[(size_t)M * KE];   // x (+t) as fp16, 68 MB
__device__ __align__(128) __half g_w[(size_t)N * KE];   // W (+2B/ws) as fp16, 34 MB

// ---------------- asm helpers ----------------
__device__ __forceinline__ uint32_t smem_u32(const void* p) {
    uint32_t a;
    asm("{ .reg .u64 t; cvta.to.shared.u64 t, %1; cvt.u32.u64 %0, t; }"
        : "=r"(a) : "l"(p));
    return a;
}
__device__ __forceinline__ void cp16(uint32_t dst, const void* src) {
    asm volatile("cp.async.cg.shared.global [%0], [%1], 16;" :: "r"(dst), "l"(src));
}
#define CP_COMMIT() asm volatile("cp.async.commit_group;" ::: "memory")
#define CP_WAIT2()  asm volatile("cp.async.wait_group 2;" ::: "memory")
#define LDM4(rr, addr) \
    asm volatile("ldmatrix.sync.aligned.m8n8.x4.shared.b16 {%0,%1,%2,%3}, [%4];" \
        : "=r"((rr)[0]), "=r"((rr)[1]), "=r"((rr)[2]), "=r"((rr)[3]) : "r"(addr))
#define MMA_F16(d, a, b) \
    asm volatile("mma.sync.aligned.m16n8k16.row.col.f32.f16.f16.f32 " \
        "{%0,%1,%2,%3}, {%4,%5,%6,%7}, {%8,%9}, {%0,%1,%2,%3};" \
        : "+f"((d)[0]), "+f"((d)[1]), "+f"((d)[2]), "+f"((d)[3]) \
        : "r"((a)[0]), "r"((a)[1]), "r"((a)[2]), "r"((a)[3]), \
          "r"((b)[0]), "r"((b)[1]))

// ============================================================
// Prep 1: x fp32 -> fp16 plane (stride KE); pad/lora cols zeroed here
// ============================================================
__global__ void conv_x_kernel(const float* __restrict__ x) {
    int i = blockIdx.x * blockDim.x + threadIdx.x;   // 4-elem group in KE row
    const int KQ = KE / 4;                            // 1040
    if (i >= M * KQ) return;
    int row = i / KQ;
    int col = (i - row * KQ) * 4;
    __half2 h0, h1;
    if (col < KX) {
        float4 v = *reinterpret_cast<const float4*>(x + (size_t)row * KX + col);
        h0 = __floats2half2_rn(v.x, v.y);
        h1 = __floats2half2_rn(v.z, v.w);
    } else {
        h0 = h1 = __floats2half2_rn(0.f, 0.f);
    }
    size_t o = (size_t)row * KE + col;
    *reinterpret_cast<__half2*>(g_x + o)     = h0;
    *reinterpret_cast<__half2*>(g_x + o + 2) = h1;
}

// ============================================================
// Prep 2: W int32 -> fp16 exact; cols [4096,4112) = (2/ws)*lB; pad zero
// ============================================================
__global__ void conv_w_kernel(const int* __restrict__ wq,
                              const float* __restrict__ ws,
                              const float* __restrict__ lB) {
    int i = blockIdx.x * blockDim.x + threadIdx.x;
    const int KQ = KE / 4;
    if (i >= N * KQ) return;
    int row = i / KQ;
    int col = (i - row * KQ) * 4;
    __half2 o0, o1;
    if (col < KX) {
        int4 v = *reinterpret_cast<const int4*>(wq + (size_t)row * KX + col);
        o0 = __floats2half2_rn((float)v.x, (float)v.y);
        o1 = __floats2half2_rn((float)v.z, (float)v.w);
    } else if (col < KX + R) {
        float inv2 = 2.0f / ws[0];
        const float* b = lB + (size_t)row * R + (col - KX);
        o0 = __floats2half2_rn(inv2 * b[0], inv2 * b[1]);
        o1 = __floats2half2_rn(inv2 * b[2], inv2 * b[3]);
    } else {
        o0 = o1 = __floats2half2_rn(0.f, 0.f);
    }
    size_t o = (size_t)row * KE + col;
    *reinterpret_cast<__half2*>(g_w + o)     = o0;
    *reinterpret_cast<__half2*>(g_w + o + 2) = o1;
}

// ============================================================
// Prep 3: t = x @ A^T (fp32), written as fp16 into lora K-columns of g_x
// ============================================================
__global__ void lora_t_kernel(const float* __restrict__ x,
                              const float* __restrict__ A) {
    __shared__ float A_s[R * 512];
    const int tid = threadIdx.x;
    const int row = tid >> 3;
    const int l8  = tid & 7;
    const int m   = blockIdx.x * 32 + row;
    float acc[R];
#pragma unroll
    for (int r = 0; r < R; r++) acc[r] = 0.f;
    for (int kc = 0; kc < KX; kc += 512) {
        __syncthreads();
        for (int i = tid; i < 2048; i += 256) {
            int rr = i >> 7, cc = i & 127;
            reinterpret_cast<float4*>(A_s)[i] =
                reinterpret_cast<const float4*>(A + (size_t)rr * KX + kc)[cc];
        }
        __syncthreads();
        const float* xr = x + (size_t)m * KX + kc;
        for (int k = l8 * 4; k < 512; k += 32) {
            float4 xv = *reinterpret_cast<const float4*>(xr + k);
#pragma unroll
            for (int r = 0; r < R; r++) {
                const float* Ar = A_s + r * 512 + k;
                acc[r] += xv.x * Ar[0] + xv.y * Ar[1] + xv.z * Ar[2] + xv.w * Ar[3];
            }
        }
    }
#pragma unroll
    for (int r = 0; r < R; r++) {
        float v = acc[r];
        v += __shfl_xor_sync(0xffffffffu, v, 1);
        v += __shfl_xor_sync(0xffffffffu, v, 2);
        v += __shfl_xor_sync(0xffffffffu, v, 4);
        if (l8 == 0) g_x[(size_t)m * KE + KX + r] = __float2half_rn(v);
    }
}

// ============================================================
// Main GEMM (HMMA fp16): out = ws * (x_ext @ W_ext^T)
// 256x128 CTA tile, 512 threads (16 warps, 4x4, warp 64x32),
// KS=64, 4-stage cp.async pipeline, mma m16n8k16 f16->f32.
// One barrier domain per SM, deeper pipeline -> more tensor work per sync.
// ============================================================
constexpr int BM = 256, BN = 128;
constexpr int KS = 64;                  // K elems per chunk (128 B/row fp16)
constexpr int PS = 4;                   // pipeline stages
constexpr int NCHUNK = KE / KS;         // 65
constexpr int ROWB = 144;               // 128 data + 16 pad (conflict-free ldmatrix)
constexpr int A_ST = BM * ROWB;         // 36864
constexpr int B_ST = BN * ROWB;         // 18432
constexpr int STAGE = A_ST + B_ST;      // 55296
constexpr int SMEM_GEMM = PS * STAGE;   // 221184 (<227KB, 1 CTA/SM)

__global__ void __launch_bounds__(512, 1)
gemm_kernel(const float* __restrict__ ws, float* __restrict__ out) {
    extern __shared__ __align__(128) char smem[];
    const uint32_t sb = smem_u32(smem);
    const int tid  = threadIdx.x;
    const int lane = tid & 31;
    const int wid  = tid >> 5;
    const int wm   = wid >> 2;          // 0..3 -> rows wm*64
    const int wn   = wid & 3;           // 0..3 -> cols wn*32
    const int m0 = blockIdx.y * BM;
    const int n0 = blockIdx.x * BN;

    // cp.async mapping: r0 = tid>>3 (0..63), c0 = (tid&7)*16 bytes
    const int r0 = tid >> 3;
    const int c0 = (tid & 7) * 16;
    const uint32_t da = (uint32_t)(r0 * ROWB + c0);
    const uint32_t db = da;                          // same pattern in B plane
    const __half* pa = g_x + (size_t)(m0 + r0) * KE + c0 / 2;
    const __half* pb = g_w + (size_t)(n0 + r0) * KE + c0 / 2;
    const size_t rstep = (size_t)64 * KE;            // 64 rows forward

    // ldmatrix lane offsets
    const int arow = wm * 64 + (lane & 15);
    const uint32_t aoff = (uint32_t)(arow * ROWB) + ((lane >> 4) * 16);
    const int brow = wn * 32 + (lane & 7) + ((lane >> 4) * 8);
    const uint32_t boff = (uint32_t)(brow * ROWB) + (((lane >> 3) & 1) * 16);

    float acc[4][4][4] = {};

    // prologue: stages 0..2 <- chunks 0..2
#pragma unroll
    for (int s = 0; s < PS - 1; s++) {
        const uint32_t st = sb + s * STAGE;
        cp16(st + da, pa);
        cp16(st + da + 64 * ROWB,  pa + rstep);
        cp16(st + da + 128 * ROWB, pa + 2 * rstep);
        cp16(st + da + 192 * ROWB, pa + 3 * rstep);
        cp16(st + A_ST + db, pb);
        cp16(st + A_ST + db + 64 * ROWB, pb + rstep);
        pa += KS; pb += KS;
        CP_COMMIT();
    }

    for (int j = 0; j < NCHUNK; j++) {
        CP_WAIT2();                       // chunk j resident; j+1,j+2 may be in flight
        __syncthreads();
        if (j + PS - 1 < NCHUNK) {        // refill stage (j+3)&3 with chunk j+3
            const uint32_t st = sb + ((j + PS - 1) & 3) * STAGE;
            cp16(st + da, pa);
            cp16(st + da + 64 * ROWB,  pa + rstep);
            cp16(st + da + 128 * ROWB, pa + 2 * rstep);
            cp16(st + da + 192 * ROWB, pa + 3 * rstep);
            cp16(st + A_ST + db, pb);
            cp16(st + A_ST + db + 64 * ROWB, pb + rstep);
            pa += KS; pb += KS;
        }
        CP_COMMIT();

        const uint32_t sa  = sb + (j & 3) * STAGE;
        const uint32_t sbp = sa + A_ST;
#pragma unroll
        for (int c = 0; c < 4; c++) {       // four k16 steps per chunk
            uint32_t af[4][4], bf[4][2];
#pragma unroll
            for (int mi = 0; mi < 4; mi++)
                LDM4(af[mi], sa + aoff + mi * (16 * ROWB) + c * 32);
#pragma unroll
            for (int jj = 0; jj < 2; jj++) {
                uint32_t r[4];
                LDM4(r, sbp + boff + jj * (16 * ROWB) + c * 32);
                bf[2 * jj][0]     = r[0];  bf[2 * jj][1]     = r[1];
                bf[2 * jj + 1][0] = r[2];  bf[2 * jj + 1][1] = r[3];
            }
#pragma unroll
            for (int mi = 0; mi < 4; mi++)
#pragma unroll
                for (int nj = 0; nj < 4; nj++)
                    MMA_F16(acc[mi][nj], af[mi], bf[nj]);
        }
    }

    // epilogue: scale by ws, store (lora already folded into K)
    const float sc = ws[0];
    const int quad = lane >> 2, qi = lane & 3;
#pragma unroll
    for (int mi = 0; mi < 4; mi++) {
        const int r = m0 + wm * 64 + mi * 16 + quad;
#pragma unroll
        for (int nj = 0; nj < 4; nj++) {
            const int cc = n0 + wn * 32 + nj * 8 + 2 * qi;
            float2 v0, v1;
            v0.x = sc * acc[mi][nj][0];
            v0.y = sc * acc[mi][nj][1];
            v1.x = sc * acc[mi][nj][2];
            v1.y = sc * acc[mi][nj][3];
            *reinterpret_cast<float2*>(out + (size_t)r * N + cc) = v0;
            *reinterpret_cast<float2*>(out + (size_t)(r + 8) * N + cc) = v1;
        }
    }
}

// ============================================================
// launch
// ============================================================
extern "C" void kernel_launch(void* const* d_in, const int* in_sizes, int n_in,
                              void* d_out, int out_size) {
    const float* x  = (const float*)d_in[0];
    const int*   wq = (const int*)d_in[1];
    const float* ws = (const float*)d_in[2];
    const float* lA = (const float*)d_in[3];
    const float* lB = (const float*)d_in[4];
    float* out = (float*)d_out;

    conv_x_kernel<<<(M * (KE / 4) + 255) / 256, 256>>>(x);
    conv_w_kernel<<<(N * (KE / 4) + 255) / 256, 256>>>(wq, ws, lB);
    lora_t_kernel<<<M / 32, 256>>>(x, lA);

    cudaFuncSetAttribute(gemm_kernel,
                         cudaFuncAttributeMaxDynamicSharedMemorySize, SMEM_GEMM);
    dim3 grid(N / BN, M / BM);   // 32 x 32
    gemm_kernel<<<grid, 512, SMEM_GEMM>>>(ws, out);
}

// round 9
// speedup vs baseline: 4.4100x; 1.0213x over previous
#include <cuda_runtime.h>
#include <cuda_fp16.h>
#include <cstdint>

// ---------------- problem dims ----------------
constexpr int M = 8192, N = 4096, KX = 4096, R = 16;
constexpr int KE = 4224;            // 4096 + 16 lora + 112 zero pad = 33*128

// ---------------- scratch ----------------
__device__ __align__(128) __half g_x[(size_t)M * KE];   // x (+t) as fp16, ~69 MB
__device__ __align__(128) __half g_w[(size_t)N * KE];   // W (+2B/ws) as fp16, ~35 MB

// ---------------- asm helpers ----------------
__device__ __forceinline__ uint32_t smem_u32(const void* p) {
    uint32_t a;
    asm("{ .reg .u64 t; cvta.to.shared.u64 t, %1; cvt.u32.u64 %0, t; }"
        : "=r"(a) : "l"(p));
    return a;
}
__device__ __forceinline__ void cp16(uint32_t dst, const void* src) {
    asm volatile("cp.async.cg.shared.global [%0], [%1], 16;" :: "r"(dst), "l"(src));
}
#define CP_COMMIT() asm volatile("cp.async.commit_group;" ::: "memory")
#define CP_WAIT0()  asm volatile("cp.async.wait_group 0;" ::: "memory")
#define LDM4(rr, addr) \
    asm volatile("ldmatrix.sync.aligned.m8n8.x4.shared.b16 {%0,%1,%2,%3}, [%4];" \
        : "=r"((rr)[0]), "=r"((rr)[1]), "=r"((rr)[2]), "=r"((rr)[3]) : "r"(addr))
#define MMA_F16(d, a, b) \
    asm volatile("mma.sync.aligned.m16n8k16.row.col.f32.f16.f16.f32 " \
        "{%0,%1,%2,%3}, {%4,%5,%6,%7}, {%8,%9}, {%0,%1,%2,%3};" \
        : "+f"((d)[0]), "+f"((d)[1]), "+f"((d)[2]), "+f"((d)[3]) \
        : "r"((a)[0]), "r"((a)[1]), "r"((a)[2]), "r"((a)[3]), \
          "r"((b)[0]), "r"((b)[1]))

// ============================================================
// Prep 1: x fp32 -> fp16 plane (stride KE); pad/lora cols zeroed here
// ============================================================
__global__ void conv_x_kernel(const float* __restrict__ x) {
    int i = blockIdx.x * blockDim.x + threadIdx.x;   // 4-elem group in KE row
    const int KQ = KE / 4;                            // 1056
    if (i >= M * KQ) return;
    int row = i / KQ;
    int col = (i - row * KQ) * 4;
    __half2 h0, h1;
    if (col < KX) {
        float4 v = *reinterpret_cast<const float4*>(x + (size_t)row * KX + col);
        h0 = __floats2half2_rn(v.x, v.y);
        h1 = __floats2half2_rn(v.z, v.w);
    } else {
        h0 = h1 = __floats2half2_rn(0.f, 0.f);
    }
    size_t o = (size_t)row * KE + col;
    *reinterpret_cast<__half2*>(g_x + o)     = h0;
    *reinterpret_cast<__half2*>(g_x + o + 2) = h1;
}

// ============================================================
// Prep 2: W int32 -> fp16 exact; cols [4096,4112) = (2/ws)*lB; pad zero
// ============================================================
__global__ void conv_w_kernel(const int* __restrict__ wq,
                              const float* __restrict__ ws,
                              const float* __restrict__ lB) {
    int i = blockIdx.x * blockDim.x + threadIdx.x;
    const int KQ = KE / 4;
    if (i >= N * KQ) return;
    int row = i / KQ;
    int col = (i - row * KQ) * 4;
    __half2 o0, o1;
    if (col < KX) {
        int4 v = *reinterpret_cast<const int4*>(wq + (size_t)row * KX + col);
        o0 = __floats2half2_rn((float)v.x, (float)v.y);
        o1 = __floats2half2_rn((float)v.z, (float)v.w);
    } else if (col < KX + R) {
        float inv2 = 2.0f / ws[0];
        const float* b = lB + (size_t)row * R + (col - KX);
        o0 = __floats2half2_rn(inv2 * b[0], inv2 * b[1]);
        o1 = __floats2half2_rn(inv2 * b[2], inv2 * b[3]);
    } else {
        o0 = o1 = __floats2half2_rn(0.f, 0.f);
    }
    size_t o = (size_t)row * KE + col;
    *reinterpret_cast<__half2*>(g_w + o)     = o0;
    *reinterpret_cast<__half2*>(g_w + o + 2) = o1;
}

// ============================================================
// Prep 3: t = x @ A^T (fp32), written as fp16 into lora K-columns of g_x
// ============================================================
__global__ void lora_t_kernel(const float* __restrict__ x,
                              const float* __restrict__ A) {
    __shared__ float A_s[R * 512];
    const int tid = threadIdx.x;
    const int row = tid >> 3;
    const int l8  = tid & 7;
    const int m   = blockIdx.x * 32 + row;
    float acc[R];
#pragma unroll
    for (int r = 0; r < R; r++) acc[r] = 0.f;
    for (int kc = 0; kc < KX; kc += 512) {
        __syncthreads();
        for (int i = tid; i < 2048; i += 256) {
            int rr = i >> 7, cc = i & 127;
            reinterpret_cast<float4*>(A_s)[i] =
                reinterpret_cast<const float4*>(A + (size_t)rr * KX + kc)[cc];
        }
        __syncthreads();
        const float* xr = x + (size_t)m * KX + kc;
        for (int k = l8 * 4; k < 512; k += 32) {
            float4 xv = *reinterpret_cast<const float4*>(xr + k);
#pragma unroll
            for (int r = 0; r < R; r++) {
                const float* Ar = A_s + r * 512 + k;
                acc[r] += xv.x * Ar[0] + xv.y * Ar[1] + xv.z * Ar[2] + xv.w * Ar[3];
            }
        }
    }
#pragma unroll
    for (int r = 0; r < R; r++) {
        float v = acc[r];
        v += __shfl_xor_sync(0xffffffffu, v, 1);
        v += __shfl_xor_sync(0xffffffffu, v, 2);
        v += __shfl_xor_sync(0xffffffffu, v, 4);
        if (l8 == 0) g_x[(size_t)m * KE + KX + r] = __float2half_rn(v);
    }
}

// ============================================================
// Main GEMM (HMMA fp16): out = ws * (x_ext @ W_ext^T)
// 256x128 CTA tile, 512 threads (16 warps, 4x4, warp 64x32),
// KS=128 (8 k16 steps per barrier), 2-stage cp.async pipeline.
// Fewer sync points -> more tensor work amortizing each barrier bubble.
// ============================================================
constexpr int BM = 256, BN = 128;
constexpr int KS = 128;                 // K elems per chunk (256 B/row fp16)
constexpr int PS = 2;                   // pipeline stages
constexpr int NCHUNK = KE / KS;         // 33
constexpr int ROWB = 272;               // 256 data + 16 pad (conflict-free ldmatrix)
constexpr int A_ST = BM * ROWB;         // 69632
constexpr int B_ST = BN * ROWB;         // 34816
constexpr int STAGE = A_ST + B_ST;      // 104448
constexpr int SMEM_GEMM = PS * STAGE;   // 208896 (<227KB, 1 CTA/SM)

__global__ void __launch_bounds__(512, 1)
gemm_kernel(const float* __restrict__ ws, float* __restrict__ out) {
    extern __shared__ __align__(128) char smem[];
    const uint32_t sb = smem_u32(smem);
    const int tid  = threadIdx.x;
    const int lane = tid & 31;
    const int wid  = tid >> 5;
    const int wm   = wid >> 2;          // 0..3 -> rows wm*64
    const int wn   = wid & 3;           // 0..3 -> cols wn*32
    const int m0 = blockIdx.y * BM;
    const int n0 = blockIdx.x * BN;

    // cp.async mapping: row = tid>>4 (0..31), seg = (tid&15)*16B within 256B row
    const int r0 = tid >> 4;
    const int c0 = (tid & 15) * 16;
    const uint32_t da = (uint32_t)(r0 * ROWB + c0);
    const __half* pa = g_x + (size_t)(m0 + r0) * KE + c0 / 2;
    const __half* pb = g_w + (size_t)(n0 + r0) * KE + c0 / 2;
    const size_t rstep = (size_t)32 * KE;            // 32 rows forward

    // ldmatrix lane offsets
    const int arow = wm * 64 + (lane & 15);
    const uint32_t aoff = (uint32_t)(arow * ROWB) + ((lane >> 4) * 16);
    const int brow = wn * 32 + (lane & 7) + ((lane >> 4) * 8);
    const uint32_t boff = (uint32_t)(brow * ROWB) + (((lane >> 3) & 1) * 16);

    float acc[4][4][4] = {};

    // prologue: stage 0 <- chunk 0
    {
        const uint32_t st = sb;
#pragma unroll
        for (int i = 0; i < 8; i++)                  // A: 256 rows, 32/pass
            cp16(st + da + i * (32 * ROWB), pa + i * rstep);
#pragma unroll
        for (int i = 0; i < 4; i++)                  // B: 128 rows
            cp16(st + A_ST + da + i * (32 * ROWB), pb + i * rstep);
        CP_COMMIT();
    }

    for (int j = 0; j < NCHUNK; j++) {
        CP_WAIT0();                       // chunk j resident
        __syncthreads();                  // all reads of chunk j-1 done too
        if (j + 1 < NCHUNK) {             // refill other stage with chunk j+1
            const uint32_t st = sb + ((j + 1) & 1) * STAGE;
            const __half* qa = pa + (size_t)(j + 1) * KS;
            const __half* qb = pb + (size_t)(j + 1) * KS;
#pragma unroll
            for (int i = 0; i < 8; i++)
                cp16(st + da + i * (32 * ROWB), qa + i * rstep);
#pragma unroll
            for (int i = 0; i < 4; i++)
                cp16(st + A_ST + da + i * (32 * ROWB), qb + i * rstep);
        }
        CP_COMMIT();

        const uint32_t sa  = sb + (j & 1) * STAGE;
        const uint32_t sbp = sa + A_ST;
#pragma unroll
        for (int c = 0; c < 8; c++) {       // eight k16 steps per chunk
            uint32_t af[4][4], bf[4][2];
#pragma unroll
            for (int mi = 0; mi < 4; mi++)
                LDM4(af[mi], sa + aoff + mi * (16 * ROWB) + c * 32);
#pragma unroll
            for (int jj = 0; jj < 2; jj++) {
                uint32_t r[4];
                LDM4(r, sbp + boff + jj * (16 * ROWB) + c * 32);
                bf[2 * jj][0]     = r[0];  bf[2 * jj][1]     = r[1];
                bf[2 * jj + 1][0] = r[2];  bf[2 * jj + 1][1] = r[3];
            }
#pragma unroll
            for (int mi = 0; mi < 4; mi++)
#pragma unroll
                for (int nj = 0; nj < 4; nj++)
                    MMA_F16(acc[mi][nj], af[mi], bf[nj]);
        }
    }

    // epilogue: scale by ws, store (lora already folded into K)
    const float sc = ws[0];
    const int quad = lane >> 2, qi = lane & 3;
#pragma unroll
    for (int mi = 0; mi < 4; mi++) {
        const int r = m0 + wm * 64 + mi * 16 + quad;
#pragma unroll
        for (int nj = 0; nj < 4; nj++) {
            const int cc = n0 + wn * 32 + nj * 8 + 2 * qi;
            float2 v0, v1;
            v0.x = sc * acc[mi][nj][0];
            v0.y = sc * acc[mi][nj][1];
            v1.x = sc * acc[mi][nj][2];
            v1.y = sc * acc[mi][nj][3];
            *reinterpret_cast<float2*>(out + (size_t)r * N + cc) = v0;
            *reinterpret_cast<float2*>(out + (size_t)(r + 8) * N + cc) = v1;
        }
    }
}

// ============================================================
// launch
// ============================================================
extern "C" void kernel_launch(void* const* d_in, const int* in_sizes, int n_in,
                              void* d_out, int out_size) {
    const float* x  = (const float*)d_in[0];
    const int*   wq = (const int*)d_in[1];
    const float* ws = (const float*)d_in[2];
    const float* lA = (const float*)d_in[3];
    const float* lB = (const float*)d_in[4];
    float* out = (float*)d_out;

    conv_x_kernel<<<(M * (KE / 4) + 255) / 256, 256>>>(x);
    conv_w_kernel<<<(N * (KE / 4) + 255) / 256, 256>>>(wq, ws, lB);
    lora_t_kernel<<<M / 32, 256>>>(x, lA);

    cudaFuncSetAttribute(gemm_kernel,
                         cudaFuncAttributeMaxDynamicSharedMemorySize, SMEM_GEMM);
    dim3 grid(N / BN, M / BM);   // 32 x 32
    gemm_kernel<<<grid, 512, SMEM_GEMM>>>(ws, out);
}